// round 13
// baseline (speedup 1.0000x reference)
#include <cuda_runtime.h>
#include <cuda_bf16.h>
#include <cstdint>

// Problem constants
#define BATCH 2
#define SEQ   2048
#define DMODEL 1024
#define NHEAD 16
#define DHEAD 64
#define BH    (BATCH * NHEAD)       // 32
#define MROWS (BATCH * SEQ)         // 4096
#define QKVN  (3 * DMODEL)          // 3072

// Scratch (device globals; no runtime allocation allowed)
// g_q/g_k store the d-dimension PERMUTED within 8-groups (i<4 -> 2i, else
// 2(i-4)+1) so mma fragment pairs (tig, tig+4) are adjacent -> LDS.64.
// S = QK^T is invariant to the shared permutation. g_v unpermuted.
__device__ float g_q[BH * SEQ * DHEAD];   // [bh][n][d'] (tf32, d-permuted)
__device__ float g_k[BH * SEQ * DHEAD];   // [bh][n][d'] (tf32, d-permuted)
__device__ float g_v[BH * SEQ * DHEAD];   // [bh][n][d]  (tf32)
__device__ float g_y[MROWS * DMODEL];     // [b*n][dmodel]
__device__ float g_wqkvT[QKVN * DMODEL];  // Wqkv^T [3072][1024] (tf32-rounded)
__device__ float g_wprojT[DMODEL * DMODEL];

// ---------------------------------------------------------------------------
__device__ __forceinline__ float tf32r(float v) {
    float r;
    asm("cvt.rna.tf32.f32 %0, %1;" : "=f"(r) : "f"(v));
    return r;
}
__device__ __forceinline__ int dperm(int c) {
    const int i = c & 7;
    return (c & ~7) | ((i < 4) ? (2 * i) : (2 * (i - 4) + 1));
}
__device__ __forceinline__ uint32_t smem_u32(const void* p) {
    uint32_t a;
    asm("{ .reg .u64 t; cvta.to.shared.u64 t, %1; cvt.u32.u64 %0, t; }" : "=r"(a) : "l"(p));
    return a;
}
__device__ __forceinline__ void cpasync16(uint32_t dst, const void* src) {
    asm volatile("cp.async.cg.shared.global [%0], [%1], 16;" :: "r"(dst), "l"(src));
}
#define CP_COMMIT() asm volatile("cp.async.commit_group;" ::: "memory")
#define CP_WAIT1()  asm volatile("cp.async.wait_group 1;" ::: "memory")
#define CP_WAIT0()  asm volatile("cp.async.wait_group 0;" ::: "memory")

// m16n8k8 tf32 MMA: D = A*B + D (fp32 accumulate). a/b are tf32 bit patterns
// (hardware reads only the tf32 bits; unrounded f32 inputs are truncated).
__device__ __forceinline__ void mma_tf32(float c[4],
                                         uint32_t a0, uint32_t a1, uint32_t a2, uint32_t a3,
                                         uint32_t b0, uint32_t b1) {
    asm volatile(
        "mma.sync.aligned.m16n8k8.row.col.f32.tf32.tf32.f32 "
        "{%0,%1,%2,%3}, {%4,%5,%6,%7}, {%8,%9}, {%0,%1,%2,%3};"
        : "+f"(c[0]), "+f"(c[1]), "+f"(c[2]), "+f"(c[3])
        : "r"(a0), "r"(a1), "r"(a2), "r"(a3), "r"(b0), "r"(b1));
}

// ---------------------------------------------------------------------------
// Transpose + tf32-round: W [rows, cols] -> WT [cols, rows]
// ---------------------------------------------------------------------------
__global__ __launch_bounds__(256) void transpose_tf32_kernel(
    const float* __restrict__ W, float* __restrict__ WT, int rows, int cols)
{
    __shared__ float t[32][33];
    const int x = blockIdx.x * 32 + threadIdx.x;
    const int y0 = blockIdx.y * 32;
#pragma unroll
    for (int i = threadIdx.y; i < 32; i += 8)
        t[i][threadIdx.x] = W[(size_t)(y0 + i) * cols + x];
    __syncthreads();
    const int ox = y0 + threadIdx.x;
    const int oy0 = blockIdx.x * 32;
#pragma unroll
    for (int i = threadIdx.y; i < 32; i += 8)
        WT[(size_t)(oy0 + i) * rows + ox] = tf32r(t[threadIdx.x][i]);
}

// ---------------------------------------------------------------------------
// tf32 mma.sync GEMM v2: cp.async double-buffered staging, no cvt in loader.
// C[128 x 128] tile = A[m0:,1024] @ BT[n0:,1024]^T + bias
// 256 threads = 8 warps; warp tile 64m x 32n; BK=32.
// mode 0: qkv scatter into g_q/g_k/g_v (tf32, q/k d-permuted); mode 1: plain
// ---------------------------------------------------------------------------
#define GK 1024
#define GBK 32
#define APAD 36   // 32 + 4 words per row
#define GSTAGE_F (2 * 128 * APAD)   // floats per stage (A+B)

__device__ __forceinline__ void gemm_stage_async(
    const float* __restrict__ A, const float* __restrict__ BT,
    int m0, int n0, int k0, float* __restrict__ sA, float* __restrict__ sB, int tid)
{
#pragma unroll
    for (int p = 0; p < 4; p++) {
        const int idx = tid + p * 256;
        const int row = idx >> 3;         // 0..127
        const int c4 = (idx & 7) * 4;     // 0..28
        cpasync16(smem_u32(&sA[row * APAD + c4]), &A[(size_t)(m0 + row) * GK + k0 + c4]);
        cpasync16(smem_u32(&sB[row * APAD + c4]), &BT[(size_t)(n0 + row) * GK + k0 + c4]);
    }
}

__global__ __launch_bounds__(256) void tc_gemm_kernel(
    const float* __restrict__ A,      // [M, 1024] row-major (raw f32 ok)
    const float* __restrict__ BT,     // [N, 1024] row-major (pre-rounded)
    const float* __restrict__ bias,   // [N]
    float* __restrict__ out,          // mode 1 only
    int mode)
{
    extern __shared__ float sm[];

    const int tid = threadIdx.x;
    const int wid = tid >> 5;
    const int lane = tid & 31;
    const int gid = lane >> 2;     // 0..7
    const int tig = lane & 3;      // 0..3
    const int mw = (wid & 1) * 64;
    const int nw = (wid >> 1) * 32;
    const int m0 = blockIdx.y * 128;
    const int n0 = blockIdx.x * 128;

    float C[4][4][4] = {};   // [mtile][ntile][c0..c3]

    // prologue: stage k-step 0
    gemm_stage_async(A, BT, m0, n0, 0, sm, sm + 128 * APAD, tid);
    CP_COMMIT();

    const int NI = GK / GBK;   // 32
    for (int i = 0; i < NI; i++) {
        const int p = i & 1;
        float* a_s = sm + p * GSTAGE_F;
        float* b_s = a_s + 128 * APAD;

        if (i + 1 < NI) {
            float* na = sm + (p ^ 1) * GSTAGE_F;
            gemm_stage_async(A, BT, m0, n0, (i + 1) * GBK, na, na + 128 * APAD, tid);
            CP_COMMIT();
            CP_WAIT1();
        } else {
            CP_WAIT0();
        }
        __syncthreads();

#pragma unroll
        for (int kk = 0; kk < 4; kk++) {
            const int kb = kk * 8;
            uint32_t af[4][4], bf[4][2];
#pragma unroll
            for (int mi = 0; mi < 4; mi++) {
                const int rb = (mw + mi * 16 + gid) * APAD + kb;
                af[mi][0] = __float_as_uint(a_s[rb + tig]);
                af[mi][1] = __float_as_uint(a_s[rb + 8 * APAD + tig]);
                af[mi][2] = __float_as_uint(a_s[rb + tig + 4]);
                af[mi][3] = __float_as_uint(a_s[rb + 8 * APAD + tig + 4]);
            }
#pragma unroll
            for (int nj = 0; nj < 4; nj++) {
                const int rb = (nw + nj * 8 + gid) * APAD + kb;
                bf[nj][0] = __float_as_uint(b_s[rb + tig]);
                bf[nj][1] = __float_as_uint(b_s[rb + tig + 4]);
            }
#pragma unroll
            for (int mi = 0; mi < 4; mi++)
#pragma unroll
                for (int nj = 0; nj < 4; nj++)
                    mma_tf32(C[mi][nj], af[mi][0], af[mi][1], af[mi][2], af[mi][3],
                             bf[nj][0], bf[nj][1]);
        }
        __syncthreads();
    }

    // Epilogue
#pragma unroll
    for (int mi = 0; mi < 4; mi++) {
#pragma unroll
        for (int rr = 0; rr < 2; rr++) {
            const int m = m0 + mw + mi * 16 + gid + rr * 8;
#pragma unroll
            for (int nj = 0; nj < 4; nj++) {
                const int n = n0 + nw + nj * 8 + 2 * tig;
                float2 v;
                v.x = C[mi][nj][rr * 2 + 0] + bias[n];
                v.y = C[mi][nj][rr * 2 + 1] + bias[n + 1];
                if (mode == 0) {
                    // tf32-round q/k/v; q/k written with d-permutation
                    v.x = tf32r(v.x); v.y = tf32r(v.y);
                    const int b = m >> 11;
                    const int nq = m & 2047;
                    const int sel = n >> 10;
                    const int h = (n & 1023) >> 6;
                    const int dd = n & 63;
                    float* dst = (sel == 0) ? g_q : (sel == 1) ? g_k : g_v;
                    float* rowp = dst + ((size_t)((b << 4) + h) * SEQ + nq) * DHEAD;
                    if (sel == 2) {
                        *(float2*)&rowp[dd] = v;
                    } else {
                        rowp[dperm(dd)] = v.x;
                        rowp[dperm(dd + 1)] = v.y;
                    }
                } else {
                    *(float2*)&out[(size_t)m * DMODEL + n] = v;
                }
            }
        }
    }
}

// ---------------------------------------------------------------------------
// Flash attention v8: BQ=256, 256 threads (8 warps x m32 warp tiles), Q in
// SMEM, 2 blocks/SM single wave. BKEY=32, cp.async double-buffered K/V,
// no-max base-2 softmax. Q/K d-permuted in gmem so S-phase fragment pairs
// load as single float2 (LDS.64) -> halves S-phase LDS issue slots.
// Dyn smem: Qs[256][68] + 2 x (Ks[32][68] + Vs[32][72]) = 105472 B.
// ---------------------------------------------------------------------------
#define KPAD 68
#define VPAD 72
#define BQ 256
#define BKEY 32
#define STAGE_F (BKEY * KPAD + BKEY * VPAD)   // floats per K/V stage
#define QS_F (BQ * KPAD)

__device__ __forceinline__ void stage_async(
    const float* __restrict__ Kg, const float* __restrict__ Vg,
    int k0, float* __restrict__ ks, float* __restrict__ vs, int tid)
{
#pragma unroll
    for (int p = 0; p < 2; p++) {
        const int idx = tid + p * 256;
        const int rr = idx >> 4;          // 0..31
        const int c4 = (idx & 15) * 4;
        cpasync16(smem_u32(&ks[rr * KPAD + c4]), &Kg[(size_t)(k0 + rr) * DHEAD + c4]);
        cpasync16(smem_u32(&vs[rr * VPAD + c4]), &Vg[(size_t)(k0 + rr) * DHEAD + c4]);
    }
}

__global__ __launch_bounds__(256, 2) void attn_tc_kernel()
{
    extern __shared__ float sm[];
    float* Qs = sm;                   // [BQ][KPAD] (d-permuted)
    float* kvs = sm + QS_F;           // 2 stages of K/V

    const int tid = threadIdx.x;
    const int wid = tid >> 5;         // 0..7
    const int lane = tid & 31;
    const int gid = lane >> 2;
    const int tig = lane & 3;
    const int t2 = 2 * tig;
    const int qw = wid * 32;          // warp q base within block

    const int qt = blockIdx.x;        // 0..7
    const int bh = blockIdx.y;
    const int q0 = qt * BQ;

    const float* Qg = g_q + (size_t)bh * SEQ * DHEAD;
    const float* Kg = g_k + (size_t)bh * SEQ * DHEAD;
    const float* Vg = g_v + (size_t)bh * SEQ * DHEAD;

    // Q scale: 1/sqrt(64) * log2(e)  (softmax done base-2)
    const float QSCALE = 0.125f * 1.4426950408889634f;

    // Stage Q once (verbatim copy of permuted gmem), scaled + rna-rounded.
#pragma unroll
    for (int p = 0; p < 16; p++) {
        const int idx = tid + p * 256;
        const int row = idx >> 4;            // 0..255
        const int c4 = (idx & 15) * 4;
        float4 v = *(const float4*)&Qg[(size_t)(q0 + row) * DHEAD + c4];
        v.x = tf32r(v.x * QSCALE); v.y = tf32r(v.y * QSCALE);
        v.z = tf32r(v.z * QSCALE); v.w = tf32r(v.w * QSCALE);
        *(float4*)&Qs[row * KPAD + c4] = v;
    }

    float O[8][2][4] = {};         // [d-tile][half][c]
    float lp[2][2] = { { 0.f, 0.f }, { 0.f, 0.f } };  // per-thread partials

    const int psrc0 = (lane & ~3) | (tig >> 1);   // gid*4 + tig/2
    const int psrc1 = psrc0 + 2;
    const bool pe = (tig & 1);

    const int NKT = SEQ / BKEY;   // 64

    // prologue: stage K/V tile 0
    stage_async(Kg, Vg, 0, kvs, kvs + BKEY * KPAD, tid);
    CP_COMMIT();

    for (int kt = 0; kt < NKT; kt++) {
        const int p = kt & 1;
        float* Ks = kvs + p * STAGE_F;
        float* Vs = Ks + BKEY * KPAD;

        if (kt + 1 < NKT) {
            float* nKs = kvs + (p ^ 1) * STAGE_F;
            stage_async(Kg, Vg, (kt + 1) * BKEY, nKs, nKs + BKEY * KPAD, tid);
            CP_COMMIT();
            CP_WAIT1();        // tile kt landed
        } else {
            CP_WAIT0();
        }
        __syncthreads();       // block-wide visibility (also fences Qs on kt=0)

        // S = Q @ K^T : 4 key n-tiles x 8 d-ksteps. Permuted layout: the
        // fragment pair (tig, tig+4) sits at (2tig, 2tig+1) -> one float2.
        float S[4][2][4] = {};
#pragma unroll
        for (int kk = 0; kk < 8; kk++) {
            const int kb = kk * 8;
            const int rb0 = (qw + gid) * KPAD + kb + t2;
            const int rb1 = (qw + 16 + gid) * KPAD + kb + t2;
            float2 qa0 = *(const float2*)&Qs[rb0];               // (a0, a2) hf0
            float2 qb0 = *(const float2*)&Qs[rb0 + 8 * KPAD];    // (a1, a3) hf0
            float2 qa1 = *(const float2*)&Qs[rb1];               // hf1
            float2 qb1 = *(const float2*)&Qs[rb1 + 8 * KPAD];
#pragma unroll
            for (int j = 0; j < 4; j++) {
                float2 kf = *(const float2*)&Ks[(j * 8 + gid) * KPAD + kb + t2];
                mma_tf32(S[j][0], __float_as_uint(qa0.x), __float_as_uint(qb0.x),
                         __float_as_uint(qa0.y), __float_as_uint(qb0.y),
                         __float_as_uint(kf.x), __float_as_uint(kf.y));
                mma_tf32(S[j][1], __float_as_uint(qa1.x), __float_as_uint(qb1.x),
                         __float_as_uint(qa1.y), __float_as_uint(qb1.y),
                         __float_as_uint(kf.x), __float_as_uint(kf.y));
            }
        }

        // P = exp2(S), accumulate per-thread row partials, tf32-round (rna,
        // unbiased -- keeps numerator consistent with f32 row sums).
#pragma unroll
        for (int j = 0; j < 4; j++) {
#pragma unroll
            for (int hf = 0; hf < 2; hf++) {
                float e0 = exp2f(S[j][hf][0]);
                float e1 = exp2f(S[j][hf][1]);
                float e2 = exp2f(S[j][hf][2]);
                float e3 = exp2f(S[j][hf][3]);
                lp[hf][0] += e0 + e1;
                lp[hf][1] += e2 + e3;
                S[j][hf][0] = tf32r(e0); S[j][hf][1] = tf32r(e1);
                S[j][hf][2] = tf32r(e2); S[j][hf][3] = tf32r(e3);
            }
        }

        // O += P @ V : 4 key-ksteps x 8 d-tiles; V b-frag shared by 2 halves
#pragma unroll
        for (int kk = 0; kk < 4; kk++) {
            const int kb = kk * 8;
            uint32_t A[2][4];
#pragma unroll
            for (int hf = 0; hf < 2; hf++) {
                float v00 = __shfl_sync(0xffffffffu, S[kk][hf][0], psrc0);
                float v01 = __shfl_sync(0xffffffffu, S[kk][hf][1], psrc0);
                float v10 = __shfl_sync(0xffffffffu, S[kk][hf][2], psrc0);
                float v11 = __shfl_sync(0xffffffffu, S[kk][hf][3], psrc0);
                float w00 = __shfl_sync(0xffffffffu, S[kk][hf][0], psrc1);
                float w01 = __shfl_sync(0xffffffffu, S[kk][hf][1], psrc1);
                float w10 = __shfl_sync(0xffffffffu, S[kk][hf][2], psrc1);
                float w11 = __shfl_sync(0xffffffffu, S[kk][hf][3], psrc1);
                A[hf][0] = __float_as_uint(pe ? v01 : v00);
                A[hf][1] = __float_as_uint(pe ? v11 : v10);
                A[hf][2] = __float_as_uint(pe ? w01 : w00);
                A[hf][3] = __float_as_uint(pe ? w11 : w10);
            }
#pragma unroll
            for (int j = 0; j < 8; j++) {
                const int nb = j * 8 + gid;
                uint32_t b0 = __float_as_uint(Vs[(kb + tig) * VPAD + nb]);
                uint32_t b1 = __float_as_uint(Vs[(kb + tig + 4) * VPAD + nb]);
                mma_tf32(O[j][0], A[0][0], A[0][1], A[0][2], A[0][3], b0, b1);
                mma_tf32(O[j][1], A[1][0], A[1][1], A[1][2], A[1][3], b0, b1);
            }
        }
        __syncthreads();       // tile kt fully consumed; buffer may be refilled
    }

    // final cross-lane row-sum reduction (once), normalize, write y
    const int b = bh >> 4;
    const int hd = bh & 15;
#pragma unroll
    for (int hf = 0; hf < 2; hf++) {
#pragma unroll
        for (int rr = 0; rr < 2; rr++) {
            float s = lp[hf][rr];
            s += __shfl_xor_sync(0xffffffffu, s, 1);
            s += __shfl_xor_sync(0xffffffffu, s, 2);
            lp[hf][rr] = 1.f / s;
        }
        const int qg0 = q0 + qw + hf * 16 + gid;
#pragma unroll
        for (int j = 0; j < 8; j++) {
            const int d = hd * 64 + j * 8 + 2 * tig;
            float2 v0 = make_float2(O[j][hf][0] * lp[hf][0], O[j][hf][1] * lp[hf][0]);
            float2 v1 = make_float2(O[j][hf][2] * lp[hf][1], O[j][hf][3] * lp[hf][1]);
            *(float2*)&g_y[(size_t)(b * SEQ + qg0) * DMODEL + d] = v0;
            *(float2*)&g_y[(size_t)(b * SEQ + qg0 + 8) * DMODEL + d] = v1;
        }
    }
}

// ---------------------------------------------------------------------------
extern "C" void kernel_launch(void* const* d_in, const int* in_sizes, int n_in,
                              void* d_out, int out_size)
{
    const float* x     = (const float*)d_in[0];   // [2,2048,1024]
    const float* Wqkv  = (const float*)d_in[1];   // [1024,3072]
    const float* bqkv  = (const float*)d_in[2];   // [3072]
    const float* Wproj = (const float*)d_in[3];   // [1024,1024]
    const float* bproj = (const float*)d_in[4];   // [1024]
    float* out = (float*)d_out;

    // Resolve DEVICE addresses of __device__ globals used as host-passed args.
    float* wqkvT;  cudaGetSymbolAddress((void**)&wqkvT, g_wqkvT);
    float* wprojT; cudaGetSymbolAddress((void**)&wprojT, g_wprojT);
    float* yptr;   cudaGetSymbolAddress((void**)&yptr, g_y);

    const int gemm_smem = 2 * GSTAGE_F * 4;               // 73728 B
    const int attn_smem = (QS_F + 2 * STAGE_F) * 4;       // 105472 B
    cudaFuncSetAttribute(tc_gemm_kernel,
                         cudaFuncAttributeMaxDynamicSharedMemorySize, gemm_smem);
    cudaFuncSetAttribute(attn_tc_kernel,
                         cudaFuncAttributeMaxDynamicSharedMemorySize, attn_smem);

    // 0) transpose + tf32-round weights
    {
        dim3 blk(32, 8);
        transpose_tf32_kernel<<<dim3(QKVN / 32, DMODEL / 32), blk>>>(Wqkv, wqkvT, DMODEL, QKVN);
        transpose_tf32_kernel<<<dim3(DMODEL / 32, DMODEL / 32), blk>>>(Wproj, wprojT, DMODEL, DMODEL);
    }
    // 1) QKV projection + head scatter (tf32; q/k d-permuted)
    {
        dim3 grid(QKVN / 128, MROWS / 128);   // (24, 32)
        tc_gemm_kernel<<<grid, 256, gemm_smem>>>(x, wqkvT, bqkv, nullptr, 0);
    }
    // 2) attention (single wave: 256 blocks x 2/SM)
    {
        dim3 grid(SEQ / BQ, BH);              // (8, 32)
        attn_tc_kernel<<<grid, 256, attn_smem>>>();
    }
    // 3) output projection
    {
        dim3 grid(DMODEL / 128, MROWS / 128); // (8, 32)
        tc_gemm_kernel<<<grid, 256, gemm_smem>>>(yptr, wprojT, bproj, out, 1);
    }
}

// round 14
// speedup vs baseline: 1.0602x; 1.0602x over previous
#include <cuda_runtime.h>
#include <cuda_bf16.h>
#include <cstdint>

// Problem constants
#define BATCH 2
#define SEQ   2048
#define DMODEL 1024
#define NHEAD 16
#define DHEAD 64
#define BH    (BATCH * NHEAD)       // 32
#define MROWS (BATCH * SEQ)         // 4096
#define QKVN  (3 * DMODEL)          // 3072

// Scratch (device globals; no runtime allocation allowed)
// g_q/g_k store the d-dimension PERMUTED within 8-groups (i<4 -> 2i, else
// 2(i-4)+1) so mma fragment pairs (tig, tig+4) are adjacent -> LDS.64.
// S = QK^T is invariant to the shared permutation. g_v unpermuted.
__device__ float g_q[BH * SEQ * DHEAD];   // [bh][n][d'] (tf32, d-permuted)
__device__ float g_k[BH * SEQ * DHEAD];   // [bh][n][d'] (tf32, d-permuted)
__device__ float g_v[BH * SEQ * DHEAD];   // [bh][n][d]  (tf32)
__device__ float g_y[MROWS * DMODEL];     // [b*n][dmodel]
__device__ float g_wqkvT[QKVN * DMODEL];  // Wqkv^T [3072][1024] (tf32-rounded)
__device__ float g_wprojT[DMODEL * DMODEL];

// ---------------------------------------------------------------------------
__device__ __forceinline__ float tf32r(float v) {
    float r;
    asm("cvt.rna.tf32.f32 %0, %1;" : "=f"(r) : "f"(v));
    return r;
}
__device__ __forceinline__ int dperm(int c) {
    const int i = c & 7;
    return (c & ~7) | ((i < 4) ? (2 * i) : (2 * (i - 4) + 1));
}
__device__ __forceinline__ uint32_t smem_u32(const void* p) {
    uint32_t a;
    asm("{ .reg .u64 t; cvta.to.shared.u64 t, %1; cvt.u32.u64 %0, t; }" : "=r"(a) : "l"(p));
    return a;
}
__device__ __forceinline__ void cpasync16(uint32_t dst, const void* src) {
    asm volatile("cp.async.cg.shared.global [%0], [%1], 16;" :: "r"(dst), "l"(src));
}
#define CP_COMMIT() asm volatile("cp.async.commit_group;" ::: "memory")
#define CP_WAIT1()  asm volatile("cp.async.wait_group 1;" ::: "memory")
#define CP_WAIT0()  asm volatile("cp.async.wait_group 0;" ::: "memory")

// m16n8k8 tf32 MMA: D = A*B + D (fp32 accumulate). a/b are tf32 bit patterns
// (hardware reads only the tf32 bits; unrounded f32 inputs are truncated).
__device__ __forceinline__ void mma_tf32(float c[4],
                                         uint32_t a0, uint32_t a1, uint32_t a2, uint32_t a3,
                                         uint32_t b0, uint32_t b1) {
    asm volatile(
        "mma.sync.aligned.m16n8k8.row.col.f32.tf32.tf32.f32 "
        "{%0,%1,%2,%3}, {%4,%5,%6,%7}, {%8,%9}, {%0,%1,%2,%3};"
        : "+f"(c[0]), "+f"(c[1]), "+f"(c[2]), "+f"(c[3])
        : "r"(a0), "r"(a1), "r"(a2), "r"(a3), "r"(b0), "r"(b1));
}

// ---------------------------------------------------------------------------
// Transpose + tf32-round: W [rows, cols] -> WT [cols, rows]
// ---------------------------------------------------------------------------
__global__ __launch_bounds__(256) void transpose_tf32_kernel(
    const float* __restrict__ W, float* __restrict__ WT, int rows, int cols)
{
    __shared__ float t[32][33];
    const int x = blockIdx.x * 32 + threadIdx.x;
    const int y0 = blockIdx.y * 32;
#pragma unroll
    for (int i = threadIdx.y; i < 32; i += 8)
        t[i][threadIdx.x] = W[(size_t)(y0 + i) * cols + x];
    __syncthreads();
    const int ox = y0 + threadIdx.x;
    const int oy0 = blockIdx.x * 32;
#pragma unroll
    for (int i = threadIdx.y; i < 32; i += 8)
        WT[(size_t)(oy0 + i) * rows + ox] = tf32r(t[threadIdx.x][i]);
}

// ---------------------------------------------------------------------------
// tf32 mma.sync GEMM v2: cp.async double-buffered staging, no cvt in loader.
// C[128 x 128] tile = A[m0:,1024] @ BT[n0:,1024]^T + bias
// 256 threads = 8 warps; warp tile 64m x 32n; BK=32.
// mode 0: qkv scatter into g_q/g_k/g_v (tf32, q/k d-permuted); mode 1: plain
// ---------------------------------------------------------------------------
#define GK 1024
#define GBK 32
#define APAD 36   // 32 + 4 words per row
#define GSTAGE_F (2 * 128 * APAD)   // floats per stage (A+B)

__device__ __forceinline__ void gemm_stage_async(
    const float* __restrict__ A, const float* __restrict__ BT,
    int m0, int n0, int k0, float* __restrict__ sA, float* __restrict__ sB, int tid)
{
#pragma unroll
    for (int p = 0; p < 4; p++) {
        const int idx = tid + p * 256;
        const int row = idx >> 3;         // 0..127
        const int c4 = (idx & 7) * 4;     // 0..28
        cpasync16(smem_u32(&sA[row * APAD + c4]), &A[(size_t)(m0 + row) * GK + k0 + c4]);
        cpasync16(smem_u32(&sB[row * APAD + c4]), &BT[(size_t)(n0 + row) * GK + k0 + c4]);
    }
}

__global__ __launch_bounds__(256) void tc_gemm_kernel(
    const float* __restrict__ A,      // [M, 1024] row-major (raw f32 ok)
    const float* __restrict__ BT,     // [N, 1024] row-major (pre-rounded)
    const float* __restrict__ bias,   // [N]
    float* __restrict__ out,          // mode 1 only
    int mode)
{
    extern __shared__ float sm[];

    const int tid = threadIdx.x;
    const int wid = tid >> 5;
    const int lane = tid & 31;
    const int gid = lane >> 2;     // 0..7
    const int tig = lane & 3;      // 0..3
    const int mw = (wid & 1) * 64;
    const int nw = (wid >> 1) * 32;
    const int m0 = blockIdx.y * 128;
    const int n0 = blockIdx.x * 128;

    float C[4][4][4] = {};   // [mtile][ntile][c0..c3]

    // prologue: stage k-step 0
    gemm_stage_async(A, BT, m0, n0, 0, sm, sm + 128 * APAD, tid);
    CP_COMMIT();

    const int NI = GK / GBK;   // 32
    for (int i = 0; i < NI; i++) {
        const int p = i & 1;
        float* a_s = sm + p * GSTAGE_F;
        float* b_s = a_s + 128 * APAD;

        if (i + 1 < NI) {
            float* na = sm + (p ^ 1) * GSTAGE_F;
            gemm_stage_async(A, BT, m0, n0, (i + 1) * GBK, na, na + 128 * APAD, tid);
            CP_COMMIT();
            CP_WAIT1();
        } else {
            CP_WAIT0();
        }
        __syncthreads();

#pragma unroll
        for (int kk = 0; kk < 4; kk++) {
            const int kb = kk * 8;
            uint32_t af[4][4], bf[4][2];
#pragma unroll
            for (int mi = 0; mi < 4; mi++) {
                const int rb = (mw + mi * 16 + gid) * APAD + kb;
                af[mi][0] = __float_as_uint(a_s[rb + tig]);
                af[mi][1] = __float_as_uint(a_s[rb + 8 * APAD + tig]);
                af[mi][2] = __float_as_uint(a_s[rb + tig + 4]);
                af[mi][3] = __float_as_uint(a_s[rb + 8 * APAD + tig + 4]);
            }
#pragma unroll
            for (int nj = 0; nj < 4; nj++) {
                const int rb = (nw + nj * 8 + gid) * APAD + kb;
                bf[nj][0] = __float_as_uint(b_s[rb + tig]);
                bf[nj][1] = __float_as_uint(b_s[rb + tig + 4]);
            }
#pragma unroll
            for (int mi = 0; mi < 4; mi++)
#pragma unroll
                for (int nj = 0; nj < 4; nj++)
                    mma_tf32(C[mi][nj], af[mi][0], af[mi][1], af[mi][2], af[mi][3],
                             bf[nj][0], bf[nj][1]);
        }
        __syncthreads();
    }

    // Epilogue
#pragma unroll
    for (int mi = 0; mi < 4; mi++) {
#pragma unroll
        for (int rr = 0; rr < 2; rr++) {
            const int m = m0 + mw + mi * 16 + gid + rr * 8;
#pragma unroll
            for (int nj = 0; nj < 4; nj++) {
                const int n = n0 + nw + nj * 8 + 2 * tig;
                float2 v;
                v.x = C[mi][nj][rr * 2 + 0] + bias[n];
                v.y = C[mi][nj][rr * 2 + 1] + bias[n + 1];
                if (mode == 0) {
                    // tf32-round q/k/v; q/k written with d-permutation
                    v.x = tf32r(v.x); v.y = tf32r(v.y);
                    const int b = m >> 11;
                    const int nq = m & 2047;
                    const int sel = n >> 10;
                    const int h = (n & 1023) >> 6;
                    const int dd = n & 63;
                    float* dst = (sel == 0) ? g_q : (sel == 1) ? g_k : g_v;
                    float* rowp = dst + ((size_t)((b << 4) + h) * SEQ + nq) * DHEAD;
                    if (sel == 2) {
                        *(float2*)&rowp[dd] = v;
                    } else {
                        rowp[dperm(dd)] = v.x;
                        rowp[dperm(dd + 1)] = v.y;
                    }
                } else {
                    *(float2*)&out[(size_t)m * DMODEL + n] = v;
                }
            }
        }
    }
}

// ---------------------------------------------------------------------------
// Flash attention v9: BQ=256, 256 threads (8 warps x m32 warp tiles), Q in
// SMEM, 2 blocks/SM single wave. BKEY=32, cp.async double-buffered K/V,
// no-max base-2 softmax. Q/K d-permuted in gmem -> fragment pairs load as
// one LDS.64. KPAD=72 (stride == 8 mod 32) makes the paired pattern
// 8*gid + 2*tig conflict-free per 16-lane phase (R13's KPAD=68 gave 4*gid
// + 2*tig -> 2-way conflicts; that was the regression).
// Dyn smem: Qs[256][72] + 2 x (Ks[32][72] + Vs[32][72]) = 110592 B.
// ---------------------------------------------------------------------------
#define KPAD 72
#define VPAD 72
#define BQ 256
#define BKEY 32
#define STAGE_F (BKEY * KPAD + BKEY * VPAD)   // floats per K/V stage
#define QS_F (BQ * KPAD)

__device__ __forceinline__ void stage_async(
    const float* __restrict__ Kg, const float* __restrict__ Vg,
    int k0, float* __restrict__ ks, float* __restrict__ vs, int tid)
{
#pragma unroll
    for (int p = 0; p < 2; p++) {
        const int idx = tid + p * 256;
        const int rr = idx >> 4;          // 0..31
        const int c4 = (idx & 15) * 4;
        cpasync16(smem_u32(&ks[rr * KPAD + c4]), &Kg[(size_t)(k0 + rr) * DHEAD + c4]);
        cpasync16(smem_u32(&vs[rr * VPAD + c4]), &Vg[(size_t)(k0 + rr) * DHEAD + c4]);
    }
}

__global__ __launch_bounds__(256, 2) void attn_tc_kernel()
{
    extern __shared__ float sm[];
    float* Qs = sm;                   // [BQ][KPAD] (d-permuted)
    float* kvs = sm + QS_F;           // 2 stages of K/V

    const int tid = threadIdx.x;
    const int wid = tid >> 5;         // 0..7
    const int lane = tid & 31;
    const int gid = lane >> 2;
    const int tig = lane & 3;
    const int t2 = 2 * tig;
    const int qw = wid * 32;          // warp q base within block

    const int qt = blockIdx.x;        // 0..7
    const int bh = blockIdx.y;
    const int q0 = qt * BQ;

    const float* Qg = g_q + (size_t)bh * SEQ * DHEAD;
    const float* Kg = g_k + (size_t)bh * SEQ * DHEAD;
    const float* Vg = g_v + (size_t)bh * SEQ * DHEAD;

    // Q scale: 1/sqrt(64) * log2(e)  (softmax done base-2)
    const float QSCALE = 0.125f * 1.4426950408889634f;

    // Stage Q once (verbatim copy of permuted gmem), scaled + rna-rounded.
#pragma unroll
    for (int p = 0; p < 16; p++) {
        const int idx = tid + p * 256;
        const int row = idx >> 4;            // 0..255
        const int c4 = (idx & 15) * 4;
        float4 v = *(const float4*)&Qg[(size_t)(q0 + row) * DHEAD + c4];
        v.x = tf32r(v.x * QSCALE); v.y = tf32r(v.y * QSCALE);
        v.z = tf32r(v.z * QSCALE); v.w = tf32r(v.w * QSCALE);
        *(float4*)&Qs[row * KPAD + c4] = v;
    }

    float O[8][2][4] = {};         // [d-tile][half][c]
    float lp[2][2] = { { 0.f, 0.f }, { 0.f, 0.f } };  // per-thread partials

    const int psrc0 = (lane & ~3) | (tig >> 1);   // gid*4 + tig/2
    const int psrc1 = psrc0 + 2;
    const bool pe = (tig & 1);

    const int NKT = SEQ / BKEY;   // 64

    // prologue: stage K/V tile 0
    stage_async(Kg, Vg, 0, kvs, kvs + BKEY * KPAD, tid);
    CP_COMMIT();

    for (int kt = 0; kt < NKT; kt++) {
        const int p = kt & 1;
        float* Ks = kvs + p * STAGE_F;
        float* Vs = Ks + BKEY * KPAD;

        if (kt + 1 < NKT) {
            float* nKs = kvs + (p ^ 1) * STAGE_F;
            stage_async(Kg, Vg, (kt + 1) * BKEY, nKs, nKs + BKEY * KPAD, tid);
            CP_COMMIT();
            CP_WAIT1();        // tile kt landed
        } else {
            CP_WAIT0();
        }
        __syncthreads();       // block-wide visibility (also fences Qs on kt=0)

        // S = Q @ K^T : 4 key n-tiles x 8 d-ksteps. Permuted layout: the
        // fragment pair (tig, tig+4) sits at (2tig, 2tig+1) -> one float2.
        float S[4][2][4] = {};
#pragma unroll
        for (int kk = 0; kk < 8; kk++) {
            const int kb = kk * 8;
            const int rb0 = (qw + gid) * KPAD + kb + t2;
            const int rb1 = (qw + 16 + gid) * KPAD + kb + t2;
            float2 qa0 = *(const float2*)&Qs[rb0];               // (a0, a2) hf0
            float2 qb0 = *(const float2*)&Qs[rb0 + 8 * KPAD];    // (a1, a3) hf0
            float2 qa1 = *(const float2*)&Qs[rb1];               // hf1
            float2 qb1 = *(const float2*)&Qs[rb1 + 8 * KPAD];
#pragma unroll
            for (int j = 0; j < 4; j++) {
                float2 kf = *(const float2*)&Ks[(j * 8 + gid) * KPAD + kb + t2];
                mma_tf32(S[j][0], __float_as_uint(qa0.x), __float_as_uint(qb0.x),
                         __float_as_uint(qa0.y), __float_as_uint(qb0.y),
                         __float_as_uint(kf.x), __float_as_uint(kf.y));
                mma_tf32(S[j][1], __float_as_uint(qa1.x), __float_as_uint(qb1.x),
                         __float_as_uint(qa1.y), __float_as_uint(qb1.y),
                         __float_as_uint(kf.x), __float_as_uint(kf.y));
            }
        }

        // P = exp2(S), accumulate per-thread row partials, tf32-round (rna,
        // unbiased -- keeps numerator consistent with f32 row sums).
#pragma unroll
        for (int j = 0; j < 4; j++) {
#pragma unroll
            for (int hf = 0; hf < 2; hf++) {
                float e0 = exp2f(S[j][hf][0]);
                float e1 = exp2f(S[j][hf][1]);
                float e2 = exp2f(S[j][hf][2]);
                float e3 = exp2f(S[j][hf][3]);
                lp[hf][0] += e0 + e1;
                lp[hf][1] += e2 + e3;
                S[j][hf][0] = tf32r(e0); S[j][hf][1] = tf32r(e1);
                S[j][hf][2] = tf32r(e2); S[j][hf][3] = tf32r(e3);
            }
        }

        // O += P @ V : 4 key-ksteps x 8 d-tiles; V b-frag shared by 2 halves
#pragma unroll
        for (int kk = 0; kk < 4; kk++) {
            const int kb = kk * 8;
            uint32_t A[2][4];
#pragma unroll
            for (int hf = 0; hf < 2; hf++) {
                float v00 = __shfl_sync(0xffffffffu, S[kk][hf][0], psrc0);
                float v01 = __shfl_sync(0xffffffffu, S[kk][hf][1], psrc0);
                float v10 = __shfl_sync(0xffffffffu, S[kk][hf][2], psrc0);
                float v11 = __shfl_sync(0xffffffffu, S[kk][hf][3], psrc0);
                float w00 = __shfl_sync(0xffffffffu, S[kk][hf][0], psrc1);
                float w01 = __shfl_sync(0xffffffffu, S[kk][hf][1], psrc1);
                float w10 = __shfl_sync(0xffffffffu, S[kk][hf][2], psrc1);
                float w11 = __shfl_sync(0xffffffffu, S[kk][hf][3], psrc1);
                A[hf][0] = __float_as_uint(pe ? v01 : v00);
                A[hf][1] = __float_as_uint(pe ? v11 : v10);
                A[hf][2] = __float_as_uint(pe ? w01 : w00);
                A[hf][3] = __float_as_uint(pe ? w11 : w10);
            }
#pragma unroll
            for (int j = 0; j < 8; j++) {
                const int nb = j * 8 + gid;
                uint32_t b0 = __float_as_uint(Vs[(kb + tig) * VPAD + nb]);
                uint32_t b1 = __float_as_uint(Vs[(kb + tig + 4) * VPAD + nb]);
                mma_tf32(O[j][0], A[0][0], A[0][1], A[0][2], A[0][3], b0, b1);
                mma_tf32(O[j][1], A[1][0], A[1][1], A[1][2], A[1][3], b0, b1);
            }
        }
        __syncthreads();       // tile kt fully consumed; buffer may be refilled
    }

    // final cross-lane row-sum reduction (once), normalize, write y
    const int b = bh >> 4;
    const int hd = bh & 15;
#pragma unroll
    for (int hf = 0; hf < 2; hf++) {
#pragma unroll
        for (int rr = 0; rr < 2; rr++) {
            float s = lp[hf][rr];
            s += __shfl_xor_sync(0xffffffffu, s, 1);
            s += __shfl_xor_sync(0xffffffffu, s, 2);
            lp[hf][rr] = 1.f / s;
        }
        const int qg0 = q0 + qw + hf * 16 + gid;
#pragma unroll
        for (int j = 0; j < 8; j++) {
            const int d = hd * 64 + j * 8 + 2 * tig;
            float2 v0 = make_float2(O[j][hf][0] * lp[hf][0], O[j][hf][1] * lp[hf][0]);
            float2 v1 = make_float2(O[j][hf][2] * lp[hf][1], O[j][hf][3] * lp[hf][1]);
            *(float2*)&g_y[(size_t)(b * SEQ + qg0) * DMODEL + d] = v0;
            *(float2*)&g_y[(size_t)(b * SEQ + qg0 + 8) * DMODEL + d] = v1;
        }
    }
}

// ---------------------------------------------------------------------------
extern "C" void kernel_launch(void* const* d_in, const int* in_sizes, int n_in,
                              void* d_out, int out_size)
{
    const float* x     = (const float*)d_in[0];   // [2,2048,1024]
    const float* Wqkv  = (const float*)d_in[1];   // [1024,3072]
    const float* bqkv  = (const float*)d_in[2];   // [3072]
    const float* Wproj = (const float*)d_in[3];   // [1024,1024]
    const float* bproj = (const float*)d_in[4];   // [1024]
    float* out = (float*)d_out;

    // Resolve DEVICE addresses of __device__ globals used as host-passed args.
    float* wqkvT;  cudaGetSymbolAddress((void**)&wqkvT, g_wqkvT);
    float* wprojT; cudaGetSymbolAddress((void**)&wprojT, g_wprojT);
    float* yptr;   cudaGetSymbolAddress((void**)&yptr, g_y);

    const int gemm_smem = 2 * GSTAGE_F * 4;               // 73728 B
    const int attn_smem = (QS_F + 2 * STAGE_F) * 4;       // 110592 B
    cudaFuncSetAttribute(tc_gemm_kernel,
                         cudaFuncAttributeMaxDynamicSharedMemorySize, gemm_smem);
    cudaFuncSetAttribute(attn_tc_kernel,
                         cudaFuncAttributeMaxDynamicSharedMemorySize, attn_smem);

    // 0) transpose + tf32-round weights
    {
        dim3 blk(32, 8);
        transpose_tf32_kernel<<<dim3(QKVN / 32, DMODEL / 32), blk>>>(Wqkv, wqkvT, DMODEL, QKVN);
        transpose_tf32_kernel<<<dim3(DMODEL / 32, DMODEL / 32), blk>>>(Wproj, wprojT, DMODEL, DMODEL);
    }
    // 1) QKV projection + head scatter (tf32; q/k d-permuted)
    {
        dim3 grid(QKVN / 128, MROWS / 128);   // (24, 32)
        tc_gemm_kernel<<<grid, 256, gemm_smem>>>(x, wqkvT, bqkv, nullptr, 0);
    }
    // 2) attention (single wave: 256 blocks x 2/SM)
    {
        dim3 grid(SEQ / BQ, BH);              // (8, 32)
        attn_tc_kernel<<<grid, 256, attn_smem>>>();
    }
    // 3) output projection
    {
        dim3 grid(DMODEL / 128, MROWS / 128); // (8, 32)
        tc_gemm_kernel<<<grid, 256, gemm_smem>>>(yptr, wprojT, bproj, out, 1);
    }
}

// round 15
// speedup vs baseline: 1.2114x; 1.1426x over previous
#include <cuda_runtime.h>
#include <cuda_bf16.h>
#include <cstdint>

// Problem constants
#define BATCH 2
#define SEQ   2048
#define DMODEL 1024
#define NHEAD 16
#define DHEAD 64
#define BH    (BATCH * NHEAD)       // 32
#define MROWS (BATCH * SEQ)         // 4096
#define QKVN  (3 * DMODEL)          // 3072

// Scratch (device globals; no runtime allocation allowed)
__device__ float g_q[BH * SEQ * DHEAD];   // [bh][n][d] (tf32-rounded)
__device__ float g_k[BH * SEQ * DHEAD];
__device__ float g_v[BH * SEQ * DHEAD];
__device__ float g_y[MROWS * DMODEL];     // [b*n][dmodel]
__device__ float g_wqkvT[QKVN * DMODEL];  // Wqkv^T [3072][1024] (tf32-rounded)
__device__ float g_wprojT[DMODEL * DMODEL];

// ---------------------------------------------------------------------------
__device__ __forceinline__ float tf32r(float v) {
    float r;
    asm("cvt.rna.tf32.f32 %0, %1;" : "=f"(r) : "f"(v));
    return r;
}
__device__ __forceinline__ uint32_t smem_u32(const void* p) {
    uint32_t a;
    asm("{ .reg .u64 t; cvta.to.shared.u64 t, %1; cvt.u32.u64 %0, t; }" : "=r"(a) : "l"(p));
    return a;
}
__device__ __forceinline__ void cpasync16(uint32_t dst, const void* src) {
    asm volatile("cp.async.cg.shared.global [%0], [%1], 16;" :: "r"(dst), "l"(src));
}
#define CP_COMMIT() asm volatile("cp.async.commit_group;" ::: "memory")
#define CP_WAIT1()  asm volatile("cp.async.wait_group 1;" ::: "memory")
#define CP_WAIT0()  asm volatile("cp.async.wait_group 0;" ::: "memory")

// m16n8k8 tf32 MMA: D = A*B + D (fp32 accumulate). a/b are tf32 bit patterns
// (hardware reads only the tf32 bits; unrounded f32 inputs are truncated).
__device__ __forceinline__ void mma_tf32(float c[4],
                                         uint32_t a0, uint32_t a1, uint32_t a2, uint32_t a3,
                                         uint32_t b0, uint32_t b1) {
    asm volatile(
        "mma.sync.aligned.m16n8k8.row.col.f32.tf32.tf32.f32 "
        "{%0,%1,%2,%3}, {%4,%5,%6,%7}, {%8,%9}, {%0,%1,%2,%3};"
        : "+f"(c[0]), "+f"(c[1]), "+f"(c[2]), "+f"(c[3])
        : "r"(a0), "r"(a1), "r"(a2), "r"(a3), "r"(b0), "r"(b1));
}

// ---------------------------------------------------------------------------
// Transpose + tf32-round: W [rows, cols] -> WT [cols, rows]
// ---------------------------------------------------------------------------
__global__ __launch_bounds__(256) void transpose_tf32_kernel(
    const float* __restrict__ W, float* __restrict__ WT, int rows, int cols)
{
    __shared__ float t[32][33];
    const int x = blockIdx.x * 32 + threadIdx.x;
    const int y0 = blockIdx.y * 32;
#pragma unroll
    for (int i = threadIdx.y; i < 32; i += 8)
        t[i][threadIdx.x] = W[(size_t)(y0 + i) * cols + x];
    __syncthreads();
    const int ox = y0 + threadIdx.x;
    const int oy0 = blockIdx.x * 32;
#pragma unroll
    for (int i = threadIdx.y; i < 32; i += 8)
        WT[(size_t)(oy0 + i) * rows + ox] = tf32r(t[threadIdx.x][i]);
}

// ---------------------------------------------------------------------------
// tf32 mma.sync GEMM v2: cp.async double-buffered staging, no cvt in loader.
// C[128 x 128] tile = A[m0:,1024] @ BT[n0:,1024]^T + bias
// 256 threads = 8 warps; warp tile 64m x 32n; BK=32.
// mode 0: qkv scatter into g_q/g_k/g_v (tf32-rounded); mode 1: row-major out
// ---------------------------------------------------------------------------
#define GK 1024
#define GBK 32
#define APAD 36   // 32 + 4 words per row
#define GSTAGE_F (2 * 128 * APAD)   // floats per stage (A+B)

__device__ __forceinline__ void gemm_stage_async(
    const float* __restrict__ A, const float* __restrict__ BT,
    int m0, int n0, int k0, float* __restrict__ sA, float* __restrict__ sB, int tid)
{
#pragma unroll
    for (int p = 0; p < 4; p++) {
        const int idx = tid + p * 256;
        const int row = idx >> 3;         // 0..127
        const int c4 = (idx & 7) * 4;     // 0..28
        cpasync16(smem_u32(&sA[row * APAD + c4]), &A[(size_t)(m0 + row) * GK + k0 + c4]);
        cpasync16(smem_u32(&sB[row * APAD + c4]), &BT[(size_t)(n0 + row) * GK + k0 + c4]);
    }
}

__global__ __launch_bounds__(256) void tc_gemm_kernel(
    const float* __restrict__ A,      // [M, 1024] row-major (raw f32 ok)
    const float* __restrict__ BT,     // [N, 1024] row-major (pre-rounded)
    const float* __restrict__ bias,   // [N]
    float* __restrict__ out,          // mode 1 only
    int mode)
{
    extern __shared__ float sm[];

    const int tid = threadIdx.x;
    const int wid = tid >> 5;
    const int lane = tid & 31;
    const int gid = lane >> 2;     // 0..7
    const int tig = lane & 3;      // 0..3
    const int mw = (wid & 1) * 64;
    const int nw = (wid >> 1) * 32;
    const int m0 = blockIdx.y * 128;
    const int n0 = blockIdx.x * 128;

    float C[4][4][4] = {};   // [mtile][ntile][c0..c3]

    // prologue: stage k-step 0
    gemm_stage_async(A, BT, m0, n0, 0, sm, sm + 128 * APAD, tid);
    CP_COMMIT();

    const int NI = GK / GBK;   // 32
    for (int i = 0; i < NI; i++) {
        const int p = i & 1;
        float* a_s = sm + p * GSTAGE_F;
        float* b_s = a_s + 128 * APAD;

        if (i + 1 < NI) {
            float* na = sm + (p ^ 1) * GSTAGE_F;
            gemm_stage_async(A, BT, m0, n0, (i + 1) * GBK, na, na + 128 * APAD, tid);
            CP_COMMIT();
            CP_WAIT1();
        } else {
            CP_WAIT0();
        }
        __syncthreads();

#pragma unroll
        for (int kk = 0; kk < 4; kk++) {
            const int kb = kk * 8;
            uint32_t af[4][4], bf[4][2];
#pragma unroll
            for (int mi = 0; mi < 4; mi++) {
                const int rb = (mw + mi * 16 + gid) * APAD + kb;
                af[mi][0] = __float_as_uint(a_s[rb + tig]);
                af[mi][1] = __float_as_uint(a_s[rb + 8 * APAD + tig]);
                af[mi][2] = __float_as_uint(a_s[rb + tig + 4]);
                af[mi][3] = __float_as_uint(a_s[rb + 8 * APAD + tig + 4]);
            }
#pragma unroll
            for (int nj = 0; nj < 4; nj++) {
                const int rb = (nw + nj * 8 + gid) * APAD + kb;
                bf[nj][0] = __float_as_uint(b_s[rb + tig]);
                bf[nj][1] = __float_as_uint(b_s[rb + tig + 4]);
            }
#pragma unroll
            for (int mi = 0; mi < 4; mi++)
#pragma unroll
                for (int nj = 0; nj < 4; nj++)
                    mma_tf32(C[mi][nj], af[mi][0], af[mi][1], af[mi][2], af[mi][3],
                             bf[nj][0], bf[nj][1]);
        }
        __syncthreads();
    }

    // Epilogue
#pragma unroll
    for (int mi = 0; mi < 4; mi++) {
#pragma unroll
        for (int rr = 0; rr < 2; rr++) {
            const int m = m0 + mw + mi * 16 + gid + rr * 8;
#pragma unroll
            for (int nj = 0; nj < 4; nj++) {
                const int n = n0 + nw + nj * 8 + 2 * tig;
                float2 v;
                v.x = C[mi][nj][rr * 2 + 0] + bias[n];
                v.y = C[mi][nj][rr * 2 + 1] + bias[n + 1];
                if (mode == 0) {
                    // tf32-round q/k/v here so attention can cp.async directly
                    v.x = tf32r(v.x); v.y = tf32r(v.y);
                    const int b = m >> 11;
                    const int nq = m & 2047;
                    const int sel = n >> 10;
                    const int h = (n & 1023) >> 6;
                    const int dd = n & 63;
                    float* dst = (sel == 0) ? g_q : (sel == 1) ? g_k : g_v;
                    *(float2*)&dst[((size_t)((b << 4) + h) * SEQ + nq) * DHEAD + dd] = v;
                } else {
                    *(float2*)&out[(size_t)m * DMODEL + n] = v;
                }
            }
        }
    }
}

// ---------------------------------------------------------------------------
// Flash attention v10: R12 base (BQ=256, 256 threads, 8 warps x m32 tiles,
// Q in SMEM, 2 blocks/SM single wave, BKEY=32, cp.async double buffer,
// no-max base-2 softmax) + ZERO-SHUFFLE PV: V key-rows are stored permuted
// within each 8-group (physical slot t holds logical key sigma(t), sigma(t)=
// 2t / 2(t-4)+1), which makes the S C-fragment (cols 2tig, 2tig+1) directly
// usable as the PV A-fragment: a = (c0, c2, c1, c3) per lane. Removes
// 64 SHFL + 32 SELP per key-tile per thread. Row sums are permutation-
// invariant; each P element multiplies its matching V row.
// Dyn smem: Qs[256][68] + 2 x (Ks[32][68] + Vs[32][72]) = 105472 B.
// ---------------------------------------------------------------------------
#define KPAD 68
#define VPAD 72
#define BQ 256
#define BKEY 32
#define STAGE_F (BKEY * KPAD + BKEY * VPAD)   // floats per K/V stage
#define QS_F (BQ * KPAD)

// sigma^{-1}(i) = (i>>1) | ((i&1)<<2): where logical key-row i is stored.
__device__ __forceinline__ int vrow_perm(int rr) {
    const int i = rr & 7;
    return (rr & ~7) | (i >> 1) | ((i & 1) << 2);
}

__device__ __forceinline__ void stage_async(
    const float* __restrict__ Kg, const float* __restrict__ Vg,
    int k0, float* __restrict__ ks, float* __restrict__ vs, int tid)
{
#pragma unroll
    for (int p = 0; p < 2; p++) {
        const int idx = tid + p * 256;
        const int rr = idx >> 4;          // 0..31 (logical key row)
        const int c4 = (idx & 15) * 4;
        cpasync16(smem_u32(&ks[rr * KPAD + c4]), &Kg[(size_t)(k0 + rr) * DHEAD + c4]);
        // V stored with permuted physical row
        cpasync16(smem_u32(&vs[vrow_perm(rr) * VPAD + c4]),
                  &Vg[(size_t)(k0 + rr) * DHEAD + c4]);
    }
}

__global__ __launch_bounds__(256, 2) void attn_tc_kernel()
{
    extern __shared__ float sm[];
    float* Qs = sm;                   // [BQ][KPAD]
    float* kvs = sm + QS_F;           // 2 stages of K/V

    const int tid = threadIdx.x;
    const int wid = tid >> 5;         // 0..7
    const int lane = tid & 31;
    const int gid = lane >> 2;
    const int tig = lane & 3;
    const int qw = wid * 32;          // warp q base within block

    const int qt = blockIdx.x;        // 0..7
    const int bh = blockIdx.y;
    const int q0 = qt * BQ;

    const float* Qg = g_q + (size_t)bh * SEQ * DHEAD;
    const float* Kg = g_k + (size_t)bh * SEQ * DHEAD;
    const float* Vg = g_v + (size_t)bh * SEQ * DHEAD;

    // Q scale: 1/sqrt(64) * log2(e)  (softmax done base-2)
    const float QSCALE = 0.125f * 1.4426950408889634f;

    // Stage Q once: 256 rows x 64 cols, scaled + rna-rounded to tf32.
#pragma unroll
    for (int p = 0; p < 16; p++) {
        const int idx = tid + p * 256;
        const int row = idx >> 4;            // 0..255
        const int c4 = (idx & 15) * 4;
        float4 v = *(const float4*)&Qg[(size_t)(q0 + row) * DHEAD + c4];
        v.x = tf32r(v.x * QSCALE); v.y = tf32r(v.y * QSCALE);
        v.z = tf32r(v.z * QSCALE); v.w = tf32r(v.w * QSCALE);
        *(float4*)&Qs[row * KPAD + c4] = v;
    }

    float O[8][2][4] = {};         // [d-tile][half][c]
    float lp[2][2] = { { 0.f, 0.f }, { 0.f, 0.f } };  // per-thread partials

    const int NKT = SEQ / BKEY;   // 64

    // prologue: stage K/V tile 0
    stage_async(Kg, Vg, 0, kvs, kvs + BKEY * KPAD, tid);
    CP_COMMIT();

    for (int kt = 0; kt < NKT; kt++) {
        const int p = kt & 1;
        float* Ks = kvs + p * STAGE_F;
        float* Vs = Ks + BKEY * KPAD;

        if (kt + 1 < NKT) {
            float* nKs = kvs + (p ^ 1) * STAGE_F;
            stage_async(Kg, Vg, (kt + 1) * BKEY, nKs, nKs + BKEY * KPAD, tid);
            CP_COMMIT();
            CP_WAIT1();        // tile kt landed
        } else {
            CP_WAIT0();
        }
        __syncthreads();       // block-wide visibility (also fences Qs on kt=0)

        // S = Q @ K^T : 4 key n-tiles x 8 d-ksteps; Q a-frags from smem,
        // K b-frags shared by both m16 halves.
        float S[4][2][4] = {};
#pragma unroll
        for (int kk = 0; kk < 8; kk++) {
            const int kb = kk * 8;
            const int rb0 = (qw + gid) * KPAD + kb;
            const int rb1 = (qw + 16 + gid) * KPAD + kb;
            uint32_t A0[4], A1[4];
            A0[0] = __float_as_uint(Qs[rb0 + tig]);
            A0[1] = __float_as_uint(Qs[rb0 + 8 * KPAD + tig]);
            A0[2] = __float_as_uint(Qs[rb0 + tig + 4]);
            A0[3] = __float_as_uint(Qs[rb0 + 8 * KPAD + tig + 4]);
            A1[0] = __float_as_uint(Qs[rb1 + tig]);
            A1[1] = __float_as_uint(Qs[rb1 + 8 * KPAD + tig]);
            A1[2] = __float_as_uint(Qs[rb1 + tig + 4]);
            A1[3] = __float_as_uint(Qs[rb1 + 8 * KPAD + tig + 4]);
#pragma unroll
            for (int j = 0; j < 4; j++) {
                const int nb = (j * 8 + gid) * KPAD + kb;
                uint32_t b0 = __float_as_uint(Ks[nb + tig]);
                uint32_t b1 = __float_as_uint(Ks[nb + tig + 4]);
                mma_tf32(S[j][0], A0[0], A0[1], A0[2], A0[3], b0, b1);
                mma_tf32(S[j][1], A1[0], A1[1], A1[2], A1[3], b0, b1);
            }
        }

        // P = exp2(S), accumulate per-thread row partials, tf32-round.
#pragma unroll
        for (int j = 0; j < 4; j++) {
#pragma unroll
            for (int hf = 0; hf < 2; hf++) {
                float e0 = exp2f(S[j][hf][0]);
                float e1 = exp2f(S[j][hf][1]);
                float e2 = exp2f(S[j][hf][2]);
                float e3 = exp2f(S[j][hf][3]);
                lp[hf][0] += e0 + e1;
                lp[hf][1] += e2 + e3;
                S[j][hf][0] = tf32r(e0); S[j][hf][1] = tf32r(e1);
                S[j][hf][2] = tf32r(e2); S[j][hf][3] = tf32r(e3);
            }
        }

        // O += P @ V : ZERO-SHUFFLE. S C-frag feeds the A-frag directly:
        // a = (c0, c2, c1, c3); V rows pre-permuted so physical slot tig
        // holds logical key 2tig and slot tig+4 holds key 2tig+1.
#pragma unroll
        for (int kk = 0; kk < 4; kk++) {
            const int kb = kk * 8;
            const uint32_t a00 = __float_as_uint(S[kk][0][0]);
            const uint32_t a01 = __float_as_uint(S[kk][0][2]);
            const uint32_t a02 = __float_as_uint(S[kk][0][1]);
            const uint32_t a03 = __float_as_uint(S[kk][0][3]);
            const uint32_t a10 = __float_as_uint(S[kk][1][0]);
            const uint32_t a11 = __float_as_uint(S[kk][1][2]);
            const uint32_t a12 = __float_as_uint(S[kk][1][1]);
            const uint32_t a13 = __float_as_uint(S[kk][1][3]);
#pragma unroll
            for (int j = 0; j < 8; j++) {
                const int nb = j * 8 + gid;
                uint32_t b0 = __float_as_uint(Vs[(kb + tig) * VPAD + nb]);
                uint32_t b1 = __float_as_uint(Vs[(kb + tig + 4) * VPAD + nb]);
                mma_tf32(O[j][0], a00, a01, a02, a03, b0, b1);
                mma_tf32(O[j][1], a10, a11, a12, a13, b0, b1);
            }
        }
        __syncthreads();       // tile kt fully consumed; buffer may be refilled
    }

    // final cross-lane row-sum reduction (once), normalize, write y
    const int b = bh >> 4;
    const int hd = bh & 15;
#pragma unroll
    for (int hf = 0; hf < 2; hf++) {
#pragma unroll
        for (int rr = 0; rr < 2; rr++) {
            float s = lp[hf][rr];
            s += __shfl_xor_sync(0xffffffffu, s, 1);
            s += __shfl_xor_sync(0xffffffffu, s, 2);
            lp[hf][rr] = 1.f / s;
        }
        const int qg0 = q0 + qw + hf * 16 + gid;
#pragma unroll
        for (int j = 0; j < 8; j++) {
            const int d = hd * 64 + j * 8 + 2 * tig;
            float2 v0 = make_float2(O[j][hf][0] * lp[hf][0], O[j][hf][1] * lp[hf][0]);
            float2 v1 = make_float2(O[j][hf][2] * lp[hf][1], O[j][hf][3] * lp[hf][1]);
            *(float2*)&g_y[(size_t)(b * SEQ + qg0) * DMODEL + d] = v0;
            *(float2*)&g_y[(size_t)(b * SEQ + qg0 + 8) * DMODEL + d] = v1;
        }
    }
}

// ---------------------------------------------------------------------------
extern "C" void kernel_launch(void* const* d_in, const int* in_sizes, int n_in,
                              void* d_out, int out_size)
{
    const float* x     = (const float*)d_in[0];   // [2,2048,1024]
    const float* Wqkv  = (const float*)d_in[1];   // [1024,3072]
    const float* bqkv  = (const float*)d_in[2];   // [3072]
    const float* Wproj = (const float*)d_in[3];   // [1024,1024]
    const float* bproj = (const float*)d_in[4];   // [1024]
    float* out = (float*)d_out;

    // Resolve DEVICE addresses of __device__ globals used as host-passed args.
    float* wqkvT;  cudaGetSymbolAddress((void**)&wqkvT, g_wqkvT);
    float* wprojT; cudaGetSymbolAddress((void**)&wprojT, g_wprojT);
    float* yptr;   cudaGetSymbolAddress((void**)&yptr, g_y);

    const int gemm_smem = 2 * GSTAGE_F * 4;               // 73728 B
    const int attn_smem = (QS_F + 2 * STAGE_F) * 4;       // 105472 B
    cudaFuncSetAttribute(tc_gemm_kernel,
                         cudaFuncAttributeMaxDynamicSharedMemorySize, gemm_smem);
    cudaFuncSetAttribute(attn_tc_kernel,
                         cudaFuncAttributeMaxDynamicSharedMemorySize, attn_smem);

    // 0) transpose + tf32-round weights
    {
        dim3 blk(32, 8);
        transpose_tf32_kernel<<<dim3(QKVN / 32, DMODEL / 32), blk>>>(Wqkv, wqkvT, DMODEL, QKVN);
        transpose_tf32_kernel<<<dim3(DMODEL / 32, DMODEL / 32), blk>>>(Wproj, wprojT, DMODEL, DMODEL);
    }
    // 1) QKV projection + head scatter (tf32-rounded)
    {
        dim3 grid(QKVN / 128, MROWS / 128);   // (24, 32)
        tc_gemm_kernel<<<grid, 256, gemm_smem>>>(x, wqkvT, bqkv, nullptr, 0);
    }
    // 2) attention (single wave: 256 blocks x 2/SM)
    {
        dim3 grid(SEQ / BQ, BH);              // (8, 32)
        attn_tc_kernel<<<grid, 256, attn_smem>>>();
    }
    // 3) output projection
    {
        dim3 grid(DMODEL / 128, MROWS / 128); // (8, 32)
        tc_gemm_kernel<<<grid, 256, gemm_smem>>>(yptr, wprojT, bproj, out, 1);
    }
}

// round 16
// speedup vs baseline: 1.2335x; 1.0182x over previous
#include <cuda_runtime.h>
#include <cuda_bf16.h>
#include <cstdint>

// Problem constants
#define BATCH 2
#define SEQ   2048
#define DMODEL 1024
#define NHEAD 16
#define DHEAD 64
#define BH    (BATCH * NHEAD)       // 32
#define MROWS (BATCH * SEQ)         // 4096
#define QKVN  (3 * DMODEL)          // 3072

// Scratch (device globals; no runtime allocation allowed)
__device__ float g_q[BH * SEQ * DHEAD];   // [bh][n][d] (tf32-rounded)
__device__ float g_k[BH * SEQ * DHEAD];
__device__ float g_v[BH * SEQ * DHEAD];
__device__ float g_y[MROWS * DMODEL];     // [b*n][dmodel]
__device__ float g_wqkvT[QKVN * DMODEL];  // Wqkv^T [3072][1024] (tf32-rounded)
__device__ float g_wprojT[DMODEL * DMODEL];

// ---------------------------------------------------------------------------
__device__ __forceinline__ float tf32r(float v) {
    float r;
    asm("cvt.rna.tf32.f32 %0, %1;" : "=f"(r) : "f"(v));
    return r;
}
__device__ __forceinline__ uint32_t smem_u32(const void* p) {
    uint32_t a;
    asm("{ .reg .u64 t; cvta.to.shared.u64 t, %1; cvt.u32.u64 %0, t; }" : "=r"(a) : "l"(p));
    return a;
}
__device__ __forceinline__ void cpasync16(uint32_t dst, const void* src) {
    asm volatile("cp.async.cg.shared.global [%0], [%1], 16;" :: "r"(dst), "l"(src));
}
#define CP_COMMIT() asm volatile("cp.async.commit_group;" ::: "memory")
#define CP_WAIT1()  asm volatile("cp.async.wait_group 1;" ::: "memory")
#define CP_WAIT0()  asm volatile("cp.async.wait_group 0;" ::: "memory")

// m16n8k8 tf32 MMA: D = A*B + D (fp32 accumulate). a/b are tf32 bit patterns
// (hardware reads only the tf32 bits; unrounded f32 inputs are truncated).
__device__ __forceinline__ void mma_tf32(float c[4],
                                         uint32_t a0, uint32_t a1, uint32_t a2, uint32_t a3,
                                         uint32_t b0, uint32_t b1) {
    asm volatile(
        "mma.sync.aligned.m16n8k8.row.col.f32.tf32.tf32.f32 "
        "{%0,%1,%2,%3}, {%4,%5,%6,%7}, {%8,%9}, {%0,%1,%2,%3};"
        : "+f"(c[0]), "+f"(c[1]), "+f"(c[2]), "+f"(c[3])
        : "r"(a0), "r"(a1), "r"(a2), "r"(a3), "r"(b0), "r"(b1));
}

// ---------------------------------------------------------------------------
// Transpose + tf32-round: W [rows, cols] -> WT [cols, rows]
// ---------------------------------------------------------------------------
__global__ __launch_bounds__(256) void transpose_tf32_kernel(
    const float* __restrict__ W, float* __restrict__ WT, int rows, int cols)
{
    __shared__ float t[32][33];
    const int x = blockIdx.x * 32 + threadIdx.x;
    const int y0 = blockIdx.y * 32;
#pragma unroll
    for (int i = threadIdx.y; i < 32; i += 8)
        t[i][threadIdx.x] = W[(size_t)(y0 + i) * cols + x];
    __syncthreads();
    const int ox = y0 + threadIdx.x;
    const int oy0 = blockIdx.x * 32;
#pragma unroll
    for (int i = threadIdx.y; i < 32; i += 8)
        WT[(size_t)(oy0 + i) * rows + ox] = tf32r(t[threadIdx.x][i]);
}

// ---------------------------------------------------------------------------
// tf32 mma.sync GEMM v3: 128x256 block tile (halves A re-read L2 traffic),
// 256 threads = 8 warps, warp tile 64x64, BK=32, cp.async double buffer.
// mode 0: qkv scatter into g_q/g_k/g_v (tf32-rounded); mode 1: row-major out
// ---------------------------------------------------------------------------
#define GK 1024
#define GBK 32
#define APAD 36   // 32 + 4 words per row
#define GBN 256
#define GSTAGE_F ((128 + GBN) * APAD)   // floats per stage (A 128 rows + B 256 rows)

__device__ __forceinline__ void gemm_stage_async(
    const float* __restrict__ A, const float* __restrict__ BT,
    int m0, int n0, int k0, float* __restrict__ sA, float* __restrict__ sB, int tid)
{
#pragma unroll
    for (int p = 0; p < 4; p++) {            // A: 128 rows x 8 float4
        const int idx = tid + p * 256;
        const int row = idx >> 3;             // 0..127
        const int c4 = (idx & 7) * 4;
        cpasync16(smem_u32(&sA[row * APAD + c4]), &A[(size_t)(m0 + row) * GK + k0 + c4]);
    }
#pragma unroll
    for (int p = 0; p < 8; p++) {            // B: 256 rows x 8 float4
        const int idx = tid + p * 256;
        const int row = idx >> 3;             // 0..255
        const int c4 = (idx & 7) * 4;
        cpasync16(smem_u32(&sB[row * APAD + c4]), &BT[(size_t)(n0 + row) * GK + k0 + c4]);
    }
}

__global__ __launch_bounds__(256, 1) void tc_gemm_kernel(
    const float* __restrict__ A,      // [M, 1024] row-major (raw f32 ok)
    const float* __restrict__ BT,     // [N, 1024] row-major (pre-rounded)
    const float* __restrict__ bias,   // [N]
    float* __restrict__ out,          // mode 1 only
    int mode)
{
    extern __shared__ float sm[];

    const int tid = threadIdx.x;
    const int wid = tid >> 5;
    const int lane = tid & 31;
    const int gid = lane >> 2;     // 0..7
    const int tig = lane & 3;      // 0..3
    const int mw = (wid & 1) * 64;        // 2 m-warps
    const int nw = (wid >> 1) * 64;       // 4 n-warps
    const int m0 = blockIdx.y * 128;
    const int n0 = blockIdx.x * GBN;

    float C[4][8][4] = {};   // [mtile][ntile][c0..c3], 128 regs

    // prologue: stage k-step 0
    gemm_stage_async(A, BT, m0, n0, 0, sm, sm + 128 * APAD, tid);
    CP_COMMIT();

    const int NI = GK / GBK;   // 32
    for (int i = 0; i < NI; i++) {
        const int p = i & 1;
        float* a_s = sm + p * GSTAGE_F;
        float* b_s = a_s + 128 * APAD;

        if (i + 1 < NI) {
            float* na = sm + (p ^ 1) * GSTAGE_F;
            gemm_stage_async(A, BT, m0, n0, (i + 1) * GBK, na, na + 128 * APAD, tid);
            CP_COMMIT();
            CP_WAIT1();
        } else {
            CP_WAIT0();
        }
        __syncthreads();

#pragma unroll
        for (int kk = 0; kk < 4; kk++) {
            const int kb = kk * 8;
            uint32_t af[4][4], bf[8][2];
#pragma unroll
            for (int mi = 0; mi < 4; mi++) {
                const int rb = (mw + mi * 16 + gid) * APAD + kb;
                af[mi][0] = __float_as_uint(a_s[rb + tig]);
                af[mi][1] = __float_as_uint(a_s[rb + 8 * APAD + tig]);
                af[mi][2] = __float_as_uint(a_s[rb + tig + 4]);
                af[mi][3] = __float_as_uint(a_s[rb + 8 * APAD + tig + 4]);
            }
#pragma unroll
            for (int nj = 0; nj < 8; nj++) {
                const int rb = (nw + nj * 8 + gid) * APAD + kb;
                bf[nj][0] = __float_as_uint(b_s[rb + tig]);
                bf[nj][1] = __float_as_uint(b_s[rb + tig + 4]);
            }
#pragma unroll
            for (int mi = 0; mi < 4; mi++)
#pragma unroll
                for (int nj = 0; nj < 8; nj++)
                    mma_tf32(C[mi][nj], af[mi][0], af[mi][1], af[mi][2], af[mi][3],
                             bf[nj][0], bf[nj][1]);
        }
        __syncthreads();
    }

    // Epilogue
#pragma unroll
    for (int mi = 0; mi < 4; mi++) {
#pragma unroll
        for (int rr = 0; rr < 2; rr++) {
            const int m = m0 + mw + mi * 16 + gid + rr * 8;
#pragma unroll
            for (int nj = 0; nj < 8; nj++) {
                const int n = n0 + nw + nj * 8 + 2 * tig;
                float2 v;
                v.x = C[mi][nj][rr * 2 + 0] + bias[n];
                v.y = C[mi][nj][rr * 2 + 1] + bias[n + 1];
                if (mode == 0) {
                    // tf32-round q/k/v here so attention can cp.async directly
                    v.x = tf32r(v.x); v.y = tf32r(v.y);
                    const int b = m >> 11;
                    const int nq = m & 2047;
                    const int sel = n >> 10;
                    const int h = (n & 1023) >> 6;
                    const int dd = n & 63;
                    float* dst = (sel == 0) ? g_q : (sel == 1) ? g_k : g_v;
                    *(float2*)&dst[((size_t)((b << 4) + h) * SEQ + nq) * DHEAD + dd] = v;
                } else {
                    *(float2*)&out[(size_t)m * DMODEL + n] = v;
                }
            }
        }
    }
}

// ---------------------------------------------------------------------------
// Flash attention v10 (R15 best, unchanged): BQ=256, 256 threads, 8 warps x
// m32 tiles, Q in SMEM, 2 blocks/SM single wave, BKEY=32, cp.async double
// buffer, no-max base-2 softmax, ZERO-SHUFFLE PV via V row permutation.
// Dyn smem: Qs[256][68] + 2 x (Ks[32][68] + Vs[32][72]) = 105472 B.
// ---------------------------------------------------------------------------
#define KPAD 68
#define VPAD 72
#define BQ 256
#define BKEY 32
#define STAGE_F (BKEY * KPAD + BKEY * VPAD)   // floats per K/V stage
#define QS_F (BQ * KPAD)

// sigma^{-1}(i) = (i>>1) | ((i&1)<<2): where logical key-row i is stored.
__device__ __forceinline__ int vrow_perm(int rr) {
    const int i = rr & 7;
    return (rr & ~7) | (i >> 1) | ((i & 1) << 2);
}

__device__ __forceinline__ void stage_async(
    const float* __restrict__ Kg, const float* __restrict__ Vg,
    int k0, float* __restrict__ ks, float* __restrict__ vs, int tid)
{
#pragma unroll
    for (int p = 0; p < 2; p++) {
        const int idx = tid + p * 256;
        const int rr = idx >> 4;          // 0..31 (logical key row)
        const int c4 = (idx & 15) * 4;
        cpasync16(smem_u32(&ks[rr * KPAD + c4]), &Kg[(size_t)(k0 + rr) * DHEAD + c4]);
        cpasync16(smem_u32(&vs[vrow_perm(rr) * VPAD + c4]),
                  &Vg[(size_t)(k0 + rr) * DHEAD + c4]);
    }
}

__global__ __launch_bounds__(256, 2) void attn_tc_kernel()
{
    extern __shared__ float sm[];
    float* Qs = sm;                   // [BQ][KPAD]
    float* kvs = sm + QS_F;           // 2 stages of K/V

    const int tid = threadIdx.x;
    const int wid = tid >> 5;         // 0..7
    const int lane = tid & 31;
    const int gid = lane >> 2;
    const int tig = lane & 3;
    const int qw = wid * 32;          // warp q base within block

    const int qt = blockIdx.x;        // 0..7
    const int bh = blockIdx.y;
    const int q0 = qt * BQ;

    const float* Qg = g_q + (size_t)bh * SEQ * DHEAD;
    const float* Kg = g_k + (size_t)bh * SEQ * DHEAD;
    const float* Vg = g_v + (size_t)bh * SEQ * DHEAD;

    // Q scale: 1/sqrt(64) * log2(e)  (softmax done base-2)
    const float QSCALE = 0.125f * 1.4426950408889634f;

    // Stage Q once: 256 rows x 64 cols, scaled + rna-rounded to tf32.
#pragma unroll
    for (int p = 0; p < 16; p++) {
        const int idx = tid + p * 256;
        const int row = idx >> 4;            // 0..255
        const int c4 = (idx & 15) * 4;
        float4 v = *(const float4*)&Qg[(size_t)(q0 + row) * DHEAD + c4];
        v.x = tf32r(v.x * QSCALE); v.y = tf32r(v.y * QSCALE);
        v.z = tf32r(v.z * QSCALE); v.w = tf32r(v.w * QSCALE);
        *(float4*)&Qs[row * KPAD + c4] = v;
    }

    float O[8][2][4] = {};         // [d-tile][half][c]
    float lp[2][2] = { { 0.f, 0.f }, { 0.f, 0.f } };  // per-thread partials

    const int NKT = SEQ / BKEY;   // 64

    // prologue: stage K/V tile 0
    stage_async(Kg, Vg, 0, kvs, kvs + BKEY * KPAD, tid);
    CP_COMMIT();

    for (int kt = 0; kt < NKT; kt++) {
        const int p = kt & 1;
        float* Ks = kvs + p * STAGE_F;
        float* Vs = Ks + BKEY * KPAD;

        if (kt + 1 < NKT) {
            float* nKs = kvs + (p ^ 1) * STAGE_F;
            stage_async(Kg, Vg, (kt + 1) * BKEY, nKs, nKs + BKEY * KPAD, tid);
            CP_COMMIT();
            CP_WAIT1();        // tile kt landed
        } else {
            CP_WAIT0();
        }
        __syncthreads();       // block-wide visibility (also fences Qs on kt=0)

        // S = Q @ K^T : 4 key n-tiles x 8 d-ksteps; Q a-frags from smem,
        // K b-frags shared by both m16 halves.
        float S[4][2][4] = {};
#pragma unroll
        for (int kk = 0; kk < 8; kk++) {
            const int kb = kk * 8;
            const int rb0 = (qw + gid) * KPAD + kb;
            const int rb1 = (qw + 16 + gid) * KPAD + kb;
            uint32_t A0[4], A1[4];
            A0[0] = __float_as_uint(Qs[rb0 + tig]);
            A0[1] = __float_as_uint(Qs[rb0 + 8 * KPAD + tig]);
            A0[2] = __float_as_uint(Qs[rb0 + tig + 4]);
            A0[3] = __float_as_uint(Qs[rb0 + 8 * KPAD + tig + 4]);
            A1[0] = __float_as_uint(Qs[rb1 + tig]);
            A1[1] = __float_as_uint(Qs[rb1 + 8 * KPAD + tig]);
            A1[2] = __float_as_uint(Qs[rb1 + tig + 4]);
            A1[3] = __float_as_uint(Qs[rb1 + 8 * KPAD + tig + 4]);
#pragma unroll
            for (int j = 0; j < 4; j++) {
                const int nb = (j * 8 + gid) * KPAD + kb;
                uint32_t b0 = __float_as_uint(Ks[nb + tig]);
                uint32_t b1 = __float_as_uint(Ks[nb + tig + 4]);
                mma_tf32(S[j][0], A0[0], A0[1], A0[2], A0[3], b0, b1);
                mma_tf32(S[j][1], A1[0], A1[1], A1[2], A1[3], b0, b1);
            }
        }

        // P = exp2(S), accumulate per-thread row partials, tf32-round.
#pragma unroll
        for (int j = 0; j < 4; j++) {
#pragma unroll
            for (int hf = 0; hf < 2; hf++) {
                float e0 = exp2f(S[j][hf][0]);
                float e1 = exp2f(S[j][hf][1]);
                float e2 = exp2f(S[j][hf][2]);
                float e3 = exp2f(S[j][hf][3]);
                lp[hf][0] += e0 + e1;
                lp[hf][1] += e2 + e3;
                S[j][hf][0] = tf32r(e0); S[j][hf][1] = tf32r(e1);
                S[j][hf][2] = tf32r(e2); S[j][hf][3] = tf32r(e3);
            }
        }

        // O += P @ V : ZERO-SHUFFLE. S C-frag feeds the A-frag directly:
        // a = (c0, c2, c1, c3); V rows pre-permuted in smem.
#pragma unroll
        for (int kk = 0; kk < 4; kk++) {
            const int kb = kk * 8;
            const uint32_t a00 = __float_as_uint(S[kk][0][0]);
            const uint32_t a01 = __float_as_uint(S[kk][0][2]);
            const uint32_t a02 = __float_as_uint(S[kk][0][1]);
            const uint32_t a03 = __float_as_uint(S[kk][0][3]);
            const uint32_t a10 = __float_as_uint(S[kk][1][0]);
            const uint32_t a11 = __float_as_uint(S[kk][1][2]);
            const uint32_t a12 = __float_as_uint(S[kk][1][1]);
            const uint32_t a13 = __float_as_uint(S[kk][1][3]);
#pragma unroll
            for (int j = 0; j < 8; j++) {
                const int nb = j * 8 + gid;
                uint32_t b0 = __float_as_uint(Vs[(kb + tig) * VPAD + nb]);
                uint32_t b1 = __float_as_uint(Vs[(kb + tig + 4) * VPAD + nb]);
                mma_tf32(O[j][0], a00, a01, a02, a03, b0, b1);
                mma_tf32(O[j][1], a10, a11, a12, a13, b0, b1);
            }
        }
        __syncthreads();       // tile kt fully consumed; buffer may be refilled
    }

    // final cross-lane row-sum reduction (once), normalize, write y
    const int b = bh >> 4;
    const int hd = bh & 15;
#pragma unroll
    for (int hf = 0; hf < 2; hf++) {
#pragma unroll
        for (int rr = 0; rr < 2; rr++) {
            float s = lp[hf][rr];
            s += __shfl_xor_sync(0xffffffffu, s, 1);
            s += __shfl_xor_sync(0xffffffffu, s, 2);
            lp[hf][rr] = 1.f / s;
        }
        const int qg0 = q0 + qw + hf * 16 + gid;
#pragma unroll
        for (int j = 0; j < 8; j++) {
            const int d = hd * 64 + j * 8 + 2 * tig;
            float2 v0 = make_float2(O[j][hf][0] * lp[hf][0], O[j][hf][1] * lp[hf][0]);
            float2 v1 = make_float2(O[j][hf][2] * lp[hf][1], O[j][hf][3] * lp[hf][1]);
            *(float2*)&g_y[(size_t)(b * SEQ + qg0) * DMODEL + d] = v0;
            *(float2*)&g_y[(size_t)(b * SEQ + qg0 + 8) * DMODEL + d] = v1;
        }
    }
}

// ---------------------------------------------------------------------------
extern "C" void kernel_launch(void* const* d_in, const int* in_sizes, int n_in,
                              void* d_out, int out_size)
{
    const float* x     = (const float*)d_in[0];   // [2,2048,1024]
    const float* Wqkv  = (const float*)d_in[1];   // [1024,3072]
    const float* bqkv  = (const float*)d_in[2];   // [3072]
    const float* Wproj = (const float*)d_in[3];   // [1024,1024]
    const float* bproj = (const float*)d_in[4];   // [1024]
    float* out = (float*)d_out;

    // Resolve DEVICE addresses of __device__ globals used as host-passed args.
    float* wqkvT;  cudaGetSymbolAddress((void**)&wqkvT, g_wqkvT);
    float* wprojT; cudaGetSymbolAddress((void**)&wprojT, g_wprojT);
    float* yptr;   cudaGetSymbolAddress((void**)&yptr, g_y);

    const int gemm_smem = 2 * GSTAGE_F * 4;               // 110592 B
    const int attn_smem = (QS_F + 2 * STAGE_F) * 4;       // 105472 B
    cudaFuncSetAttribute(tc_gemm_kernel,
                         cudaFuncAttributeMaxDynamicSharedMemorySize, gemm_smem);
    cudaFuncSetAttribute(attn_tc_kernel,
                         cudaFuncAttributeMaxDynamicSharedMemorySize, attn_smem);

    // 0) transpose + tf32-round weights
    {
        dim3 blk(32, 8);
        transpose_tf32_kernel<<<dim3(QKVN / 32, DMODEL / 32), blk>>>(Wqkv, wqkvT, DMODEL, QKVN);
        transpose_tf32_kernel<<<dim3(DMODEL / 32, DMODEL / 32), blk>>>(Wproj, wprojT, DMODEL, DMODEL);
    }
    // 1) QKV projection + head scatter (tf32-rounded)
    {
        dim3 grid(QKVN / GBN, MROWS / 128);   // (12, 32)
        tc_gemm_kernel<<<grid, 256, gemm_smem>>>(x, wqkvT, bqkv, nullptr, 0);
    }
    // 2) attention (single wave: 256 blocks x 2/SM)
    {
        dim3 grid(SEQ / BQ, BH);              // (8, 32)
        attn_tc_kernel<<<grid, 256, attn_smem>>>();
    }
    // 3) output projection
    {
        dim3 grid(DMODEL / GBN, MROWS / 128); // (4, 32)
        tc_gemm_kernel<<<grid, 256, gemm_smem>>>(yptr, wprojT, bproj, out, 1);
    }
}